// round 2
// baseline (speedup 1.0000x reference)
#include <cuda_runtime.h>

// InstantNGPMLP: (N,32) -> relu(L) -> relu(L) -> relu(L) -> L -> (N,16), fp32.
// Packed fma.rn.f32x2 path (2 FMAs/instr). Weights in SMEM (broadcast LDS.128);
// per-thread activations in warp-transposed SMEM. R1 fix: no minBlocks launch
// bound (allow up to 255 regs -> no spill -> no lmem pool allocation), and
// layer-1 x streamed in float4 chunks instead of a 32-reg array.

typedef unsigned long long u64;

#define THREADS 256
#define RPT 4   // rows per thread; grid = N / (THREADS*RPT) = 1024

// SMEM layout (float offsets)
#define W1_OFF 0                 // 32*64   = 2048
#define B1_OFF 2048              // 64
#define W2_OFF 2112              // 64*64   = 4096
#define B2_OFF 6208              // 64
#define W3_OFF 6272              // 64*64   = 4096
#define B3_OFF 10368             // 64
#define W4_OFF 10432             // 64*16   = 1024
#define B4_OFF 11456             // 16
#define H_OFF  11472             // THREADS*64 = 16384
#define SMEM_FLOATS (H_OFF + THREADS * 64)
#define SMEM_BYTES  (SMEM_FLOATS * 4)

__device__ __forceinline__ u64 fma2(u64 a, u64 b, u64 c) {
    u64 d;
    asm("fma.rn.f32x2 %0, %1, %2, %3;" : "=l"(d) : "l"(a), "l"(b), "l"(c));
    return d;
}
__device__ __forceinline__ u64 pack2(float x) {
    u64 d;
    asm("mov.b64 %0, {%1, %1};" : "=l"(d) : "f"(x));
    return d;
}
__device__ __forceinline__ void unpack2(u64 v, float& x, float& y) {
    asm("mov.b64 {%0, %1}, %2;" : "=f"(x), "=f"(y) : "l"(v));
}

// One 64->64 relu layer: reads h from Hs[k*32], writes relu result back.
// Safe without fences: all reads complete (feed acc) before any write.
__device__ __forceinline__ void layer64_relu(const float* __restrict__ s,
                                             int woff, int boff,
                                             float* __restrict__ Hs) {
    u64 acc[32];
    {
        const ulonglong2* B = (const ulonglong2*)(s + boff);
#pragma unroll
        for (int i = 0; i < 16; i++) {
            ulonglong2 t = B[i];
            acc[2 * i] = t.x;
            acc[2 * i + 1] = t.y;
        }
    }
#pragma unroll 4
    for (int k = 0; k < 64; k++) {
        u64 hk = pack2(Hs[k * 32]);
        const ulonglong2* Wr = (const ulonglong2*)(s + woff + k * 64);
#pragma unroll
        for (int i = 0; i < 16; i++) {
            ulonglong2 w = Wr[i];
            acc[2 * i]     = fma2(hk, w.x, acc[2 * i]);
            acc[2 * i + 1] = fma2(hk, w.y, acc[2 * i + 1]);
        }
    }
#pragma unroll
    for (int i = 0; i < 32; i++) {
        float a, b;
        unpack2(acc[i], a, b);
        Hs[(2 * i) * 32]     = fmaxf(a, 0.0f);
        Hs[(2 * i + 1) * 32] = fmaxf(b, 0.0f);
    }
}

__global__ void __launch_bounds__(THREADS)
mlp_kernel(const float* __restrict__ x,
           const float* __restrict__ Wi, const float* __restrict__ bi,
           const float* __restrict__ W1, const float* __restrict__ b1,
           const float* __restrict__ W2, const float* __restrict__ b2,
           const float* __restrict__ Wo, const float* __restrict__ bo,
           float* __restrict__ out) {
    extern __shared__ float s[];
    const int tid = threadIdx.x;

    // Stage weights + biases into SMEM (once per CTA).
    for (int i = tid; i < 2048; i += THREADS) s[W1_OFF + i] = Wi[i];
    for (int i = tid; i < 64;   i += THREADS) s[B1_OFF + i] = bi[i];
    for (int i = tid; i < 4096; i += THREADS) s[W2_OFF + i] = W1[i];
    for (int i = tid; i < 64;   i += THREADS) s[B2_OFF + i] = b1[i];
    for (int i = tid; i < 4096; i += THREADS) s[W3_OFF + i] = W2[i];
    for (int i = tid; i < 64;   i += THREADS) s[B3_OFF + i] = b2[i];
    for (int i = tid; i < 1024; i += THREADS) s[W4_OFF + i] = Wo[i];
    for (int i = tid; i < 16;   i += THREADS) s[B4_OFF + i] = bo[i];
    __syncthreads();

    // Warp-transposed per-thread activation array: h[k] at Hs[k*32].
    float* Hs = s + H_OFF + (tid >> 5) * (32 * 64) + (tid & 31);

#pragma unroll 1
    for (int r = 0; r < RPT; r++) {
        const int row = blockIdx.x * (THREADS * RPT) + r * THREADS + tid;

        u64 acc[32];
        {
            const ulonglong2* B = (const ulonglong2*)(s + B1_OFF);
#pragma unroll
            for (int i = 0; i < 16; i++) {
                ulonglong2 t = B[i];
                acc[2 * i] = t.x;
                acc[2 * i + 1] = t.y;
            }
        }

        // ---- Layer 1: 32 -> 64. Stream x in float4 chunks (low reg pressure).
        {
            const float4* xv = (const float4*)(x + (size_t)row * 32);
#pragma unroll
            for (int c = 0; c < 8; c++) {
                float4 v = xv[c];
                float xk[4] = {v.x, v.y, v.z, v.w};
#pragma unroll
                for (int j = 0; j < 4; j++) {
                    int k = c * 4 + j;
                    u64 hk = pack2(xk[j]);
                    const ulonglong2* Wr = (const ulonglong2*)(s + W1_OFF + k * 64);
#pragma unroll
                    for (int i = 0; i < 16; i++) {
                        ulonglong2 w = Wr[i];
                        acc[2 * i]     = fma2(hk, w.x, acc[2 * i]);
                        acc[2 * i + 1] = fma2(hk, w.y, acc[2 * i + 1]);
                    }
                }
            }
        }
#pragma unroll
        for (int i = 0; i < 32; i++) {
            float a, b;
            unpack2(acc[i], a, b);
            Hs[(2 * i) * 32]     = fmaxf(a, 0.0f);
            Hs[(2 * i + 1) * 32] = fmaxf(b, 0.0f);
        }

        // ---- Layers 2, 3: 64 -> 64 + relu ----
        layer64_relu(s, W2_OFF, B2_OFF, Hs);
        layer64_relu(s, W3_OFF, B3_OFF, Hs);

        // ---- Layer 4: 64 -> 16 (no relu) ----
        u64 acc4[8];
        {
            const ulonglong2* B = (const ulonglong2*)(s + B4_OFF);
#pragma unroll
            for (int i = 0; i < 4; i++) {
                ulonglong2 t = B[i];
                acc4[2 * i] = t.x;
                acc4[2 * i + 1] = t.y;
            }
        }
#pragma unroll 8
        for (int k = 0; k < 64; k++) {
            u64 hk = pack2(Hs[k * 32]);
            const ulonglong2* Wr = (const ulonglong2*)(s + W4_OFF + k * 16);
#pragma unroll
            for (int i = 0; i < 4; i++) {
                ulonglong2 w = Wr[i];
                acc4[2 * i]     = fma2(hk, w.x, acc4[2 * i]);
                acc4[2 * i + 1] = fma2(hk, w.y, acc4[2 * i + 1]);
            }
        }
        float o[16];
#pragma unroll
        for (int i = 0; i < 8; i++) unpack2(acc4[i], o[2 * i], o[2 * i + 1]);

        float4* ov = (float4*)(out + (size_t)row * 16);
        ov[0] = make_float4(o[0],  o[1],  o[2],  o[3]);
        ov[1] = make_float4(o[4],  o[5],  o[6],  o[7]);
        ov[2] = make_float4(o[8],  o[9],  o[10], o[11]);
        ov[3] = make_float4(o[12], o[13], o[14], o[15]);
    }
}

extern "C" void kernel_launch(void* const* d_in, const int* in_sizes, int n_in,
                              void* d_out, int out_size) {
    (void)in_sizes; (void)n_in; (void)out_size;
    const float* x  = (const float*)d_in[0];
    const float* Wi = (const float*)d_in[1];
    const float* bi = (const float*)d_in[2];
    const float* W1 = (const float*)d_in[3];
    const float* b1 = (const float*)d_in[4];
    const float* W2 = (const float*)d_in[5];
    const float* b2 = (const float*)d_in[6];
    const float* Wo = (const float*)d_in[7];
    const float* bo = (const float*)d_in[8];
    float* out = (float*)d_out;

    cudaFuncSetAttribute(mlp_kernel,
                         cudaFuncAttributeMaxDynamicSharedMemorySize, SMEM_BYTES);

    const int N = 1048576;
    const int grid = N / (THREADS * RPT);  // 1024
    mlp_kernel<<<grid, THREADS, SMEM_BYTES>>>(x, Wi, bi, W1, b1, W2, b2, Wo, bo, out);
}

// round 3
// speedup vs baseline: 2.1659x; 2.1659x over previous
#include <cuda_runtime.h>

// InstantNGPMLP: (N,32) -> relu(L) x3 -> L -> (N,16), fp32.
// Packed fma.rn.f32x2 (2 FMAs/instr). Weights staged in SMEM (broadcast
// LDS.128), per-thread activations in warp-transposed SMEM.
// R3 changes vs R2 (2047us, regs=254, occ=12.3%, issue=16.2%):
//   - k-loop unroll 1 + two 8-load sub-blocks -> live regs ~110 (was ~250)
//   - __launch_bounds__(256, 2) -> 128-reg cap -> 2 CTAs/SM, occ 25%
// Goal: convert latency-starved issue (16%) into fma/LDS-pipe-bound (~50-60%).

typedef unsigned long long u64;

#define THREADS 256
#define RPT 4   // rows per thread; grid = N / (THREADS*RPT) = 1024

// SMEM layout (float offsets)
#define W1_OFF 0                 // 32*64   = 2048
#define B1_OFF 2048              // 64
#define W2_OFF 2112              // 64*64   = 4096
#define B2_OFF 6208              // 64
#define W3_OFF 6272              // 64*64   = 4096
#define B3_OFF 10368             // 64
#define W4_OFF 10432             // 64*16   = 1024
#define B4_OFF 11456             // 16
#define H_OFF  11472             // THREADS*64 = 16384
#define SMEM_FLOATS (H_OFF + THREADS * 64)
#define SMEM_BYTES  (SMEM_FLOATS * 4)

__device__ __forceinline__ u64 fma2(u64 a, u64 b, u64 c) {
    u64 d;
    asm("fma.rn.f32x2 %0, %1, %2, %3;" : "=l"(d) : "l"(a), "l"(b), "l"(c));
    return d;
}
__device__ __forceinline__ u64 pack2(float x) {
    u64 d;
    asm("mov.b64 %0, {%1, %1};" : "=l"(d) : "f"(x));
    return d;
}
__device__ __forceinline__ void unpack2(u64 v, float& x, float& y) {
    asm("mov.b64 {%0, %1}, %2;" : "=f"(x), "=f"(y) : "l"(v));
}

// One 64->64 relu layer: reads h from Hs[k*32], writes relu result back.
// Safe without fences: all reads complete (feed acc) before any write.
__device__ __forceinline__ void layer64_relu(const float* __restrict__ s,
                                             int woff, int boff,
                                             float* __restrict__ Hs) {
    u64 acc[32];
    {
        const ulonglong2* B = (const ulonglong2*)(s + boff);
#pragma unroll
        for (int i = 0; i < 16; i++) {
            ulonglong2 t = B[i];
            acc[2 * i] = t.x;
            acc[2 * i + 1] = t.y;
        }
    }
#pragma unroll 1
    for (int k = 0; k < 64; k++) {
        u64 hk = pack2(Hs[k * 32]);
        const ulonglong2* Wr = (const ulonglong2*)(s + woff + k * 64);
        // two sub-blocks of 8 loads + 16 fma2 to bound live registers
#pragma unroll
        for (int i = 0; i < 8; i++) {
            ulonglong2 w = Wr[i];
            acc[2 * i]     = fma2(hk, w.x, acc[2 * i]);
            acc[2 * i + 1] = fma2(hk, w.y, acc[2 * i + 1]);
        }
#pragma unroll
        for (int i = 8; i < 16; i++) {
            ulonglong2 w = Wr[i];
            acc[2 * i]     = fma2(hk, w.x, acc[2 * i]);
            acc[2 * i + 1] = fma2(hk, w.y, acc[2 * i + 1]);
        }
    }
#pragma unroll
    for (int i = 0; i < 32; i++) {
        float a, b;
        unpack2(acc[i], a, b);
        Hs[(2 * i) * 32]     = fmaxf(a, 0.0f);
        Hs[(2 * i + 1) * 32] = fmaxf(b, 0.0f);
    }
}

__global__ void __launch_bounds__(THREADS, 2)
mlp_kernel(const float* __restrict__ x,
           const float* __restrict__ Wi, const float* __restrict__ bi,
           const float* __restrict__ W1, const float* __restrict__ b1,
           const float* __restrict__ W2, const float* __restrict__ b2,
           const float* __restrict__ Wo, const float* __restrict__ bo,
           float* __restrict__ out) {
    extern __shared__ float s[];
    const int tid = threadIdx.x;

    // Stage weights + biases into SMEM (once per CTA).
    for (int i = tid; i < 2048; i += THREADS) s[W1_OFF + i] = Wi[i];
    for (int i = tid; i < 64;   i += THREADS) s[B1_OFF + i] = bi[i];
    for (int i = tid; i < 4096; i += THREADS) s[W2_OFF + i] = W1[i];
    for (int i = tid; i < 64;   i += THREADS) s[B2_OFF + i] = b1[i];
    for (int i = tid; i < 4096; i += THREADS) s[W3_OFF + i] = W2[i];
    for (int i = tid; i < 64;   i += THREADS) s[B3_OFF + i] = b2[i];
    for (int i = tid; i < 1024; i += THREADS) s[W4_OFF + i] = Wo[i];
    for (int i = tid; i < 16;   i += THREADS) s[B4_OFF + i] = bo[i];
    __syncthreads();

    // Warp-transposed per-thread activation array: h[k] at Hs[k*32].
    float* Hs = s + H_OFF + (tid >> 5) * (32 * 64) + (tid & 31);

#pragma unroll 1
    for (int r = 0; r < RPT; r++) {
        const int row = blockIdx.x * (THREADS * RPT) + r * THREADS + tid;

        u64 acc[32];
        {
            const ulonglong2* B = (const ulonglong2*)(s + B1_OFF);
#pragma unroll
            for (int i = 0; i < 16; i++) {
                ulonglong2 t = B[i];
                acc[2 * i] = t.x;
                acc[2 * i + 1] = t.y;
            }
        }

        // ---- Layer 1: 32 -> 64. Stream x in float4 chunks (low reg pressure).
        {
            const float4* xv = (const float4*)(x + (size_t)row * 32);
#pragma unroll 1
            for (int c = 0; c < 8; c++) {
                float4 v = xv[c];
                float xk[4] = {v.x, v.y, v.z, v.w};
#pragma unroll
                for (int j = 0; j < 4; j++) {
                    int k = c * 4 + j;
                    u64 hk = pack2(xk[j]);
                    const ulonglong2* Wr = (const ulonglong2*)(s + W1_OFF + k * 64);
#pragma unroll
                    for (int i = 0; i < 8; i++) {
                        ulonglong2 w = Wr[i];
                        acc[2 * i]     = fma2(hk, w.x, acc[2 * i]);
                        acc[2 * i + 1] = fma2(hk, w.y, acc[2 * i + 1]);
                    }
#pragma unroll
                    for (int i = 8; i < 16; i++) {
                        ulonglong2 w = Wr[i];
                        acc[2 * i]     = fma2(hk, w.x, acc[2 * i]);
                        acc[2 * i + 1] = fma2(hk, w.y, acc[2 * i + 1]);
                    }
                }
            }
        }
#pragma unroll
        for (int i = 0; i < 32; i++) {
            float a, b;
            unpack2(acc[i], a, b);
            Hs[(2 * i) * 32]     = fmaxf(a, 0.0f);
            Hs[(2 * i + 1) * 32] = fmaxf(b, 0.0f);
        }

        // ---- Layers 2, 3: 64 -> 64 + relu ----
        layer64_relu(s, W2_OFF, B2_OFF, Hs);
        layer64_relu(s, W3_OFF, B3_OFF, Hs);

        // ---- Layer 4: 64 -> 16 (no relu) ----
        u64 acc4[8];
        {
            const ulonglong2* B = (const ulonglong2*)(s + B4_OFF);
#pragma unroll
            for (int i = 0; i < 4; i++) {
                ulonglong2 t = B[i];
                acc4[2 * i] = t.x;
                acc4[2 * i + 1] = t.y;
            }
        }
#pragma unroll 2
        for (int k = 0; k < 64; k++) {
            u64 hk = pack2(Hs[k * 32]);
            const ulonglong2* Wr = (const ulonglong2*)(s + W4_OFF + k * 16);
#pragma unroll
            for (int i = 0; i < 4; i++) {
                ulonglong2 w = Wr[i];
                acc4[2 * i]     = fma2(hk, w.x, acc4[2 * i]);
                acc4[2 * i + 1] = fma2(hk, w.y, acc4[2 * i + 1]);
            }
        }
        float o[16];
#pragma unroll
        for (int i = 0; i < 8; i++) unpack2(acc4[i], o[2 * i], o[2 * i + 1]);

        float4* ov = (float4*)(out + (size_t)row * 16);
        ov[0] = make_float4(o[0],  o[1],  o[2],  o[3]);
        ov[1] = make_float4(o[4],  o[5],  o[6],  o[7]);
        ov[2] = make_float4(o[8],  o[9],  o[10], o[11]);
        ov[3] = make_float4(o[12], o[13], o[14], o[15]);
    }
}

extern "C" void kernel_launch(void* const* d_in, const int* in_sizes, int n_in,
                              void* d_out, int out_size) {
    (void)in_sizes; (void)n_in; (void)out_size;
    const float* x  = (const float*)d_in[0];
    const float* Wi = (const float*)d_in[1];
    const float* bi = (const float*)d_in[2];
    const float* W1 = (const float*)d_in[3];
    const float* b1 = (const float*)d_in[4];
    const float* W2 = (const float*)d_in[5];
    const float* b2 = (const float*)d_in[6];
    const float* Wo = (const float*)d_in[7];
    const float* bo = (const float*)d_in[8];
    float* out = (float*)d_out;

    cudaFuncSetAttribute(mlp_kernel,
                         cudaFuncAttributeMaxDynamicSharedMemorySize, SMEM_BYTES);

    const int N = 1048576;
    const int grid = N / (THREADS * RPT);  // 1024
    mlp_kernel<<<grid, THREADS, SMEM_BYTES>>>(x, Wi, bi, W1, b1, W2, b2, Wo, bo, out);
}

// round 5
// speedup vs baseline: 10.3719x; 4.7887x over previous
#include <cuda_runtime.h>
#include <cuda_fp16.h>
#include <cstdint>

// InstantNGPMLP fused on mma.sync (HMMA, arch-portable PTX — tcgen05 is not
// available under this harness's compute_103 virtual arch).
// (N,32) -> relu(64) -> relu(64) -> relu(64) -> (16), fp32 I/O.
//
// One warp owns 16 rows end-to-end. D(m16n8) fragments of two adjacent
// n-tiles ARE the A(m16k16) fragment of the next layer -> register-only
// relu/bias/convert between layers; no smem for activations.
//
// Precision: full hi/lo fp16 split (3-term mma: Ah*Bh + Al*Bh + Ah*Bl),
// fp32 accumulate -> rel_err ~1e-6 (fp16-only would be ~8e-4, too risky).
// Weights pre-split into fragment-ordered smem arrays once per CTA.

#define THREADS 128
#define WARPS 4
#define NROWS 1048576
#define WTILES (NROWS / 16)   // 65536 warp-tiles
#define GRID 592              // 4 CTAs/SM * 148

__device__ __forceinline__ void mma16816(float d[4], const uint32_t* a, uint32_t b0, uint32_t b1) {
    asm volatile(
        "mma.sync.aligned.m16n8k16.row.col.f32.f16.f16.f32 "
        "{%0,%1,%2,%3}, {%4,%5,%6,%7}, {%8,%9}, {%0,%1,%2,%3};"
        : "+f"(d[0]), "+f"(d[1]), "+f"(d[2]), "+f"(d[3])
        : "r"(a[0]), "r"(a[1]), "r"(a[2]), "r"(a[3]), "r"(b0), "r"(b1));
}

__device__ __forceinline__ void pack_hl(float f0, float f1, uint32_t& hi, uint32_t& lo) {
    __half h0 = __float2half_rn(f0);
    __half h1 = __float2half_rn(f1);
    __half l0 = __float2half_rn(f0 - __half2float(h0));
    __half l1 = __float2half_rn(f1 - __half2float(h1));
    hi = (uint32_t)__half_as_ushort(h0) | ((uint32_t)__half_as_ushort(h1) << 16);
    lo = (uint32_t)__half_as_ushort(l0) | ((uint32_t)__half_as_ushort(l1) << 16);
}

// ---- static smem: weight fragments (hi/lo) + biases = 45.9 KB ----
__shared__ uint32_t sf1h[1024], sf1l[1024];   // L1: K=32 (2 ks) x 8 nf
__shared__ uint32_t sf2h[2048], sf2l[2048];   // L2: K=64 (4 ks) x 8 nf
__shared__ uint32_t sf3h[2048], sf3l[2048];   // L3
__shared__ uint32_t sf4h[512],  sf4l[512];    // L4: 4 ks x 2 nf
__shared__ float sb1[64], sb2[64], sb3[64], sb4[16];

// Stage W (K x N row-major, fp32) into hi/lo mma-B-fragment order.
// Fragment f = ks*NF + j; per (f, lane): 2 b32 regs.
// b0 = { B[16ks+2t][8j+g], B[16ks+2t+1][..] }, b1 = same with k+8.
__device__ void stage(const float* __restrict__ W, int K, int N,
                      uint32_t* hi, uint32_t* lo, int tid) {
    const int KS = K / 16, NF = N / 8, total = KS * NF * 32;
    for (int idx = tid; idx < total; idx += THREADS) {
        int lane = idx & 31, f = idx >> 5;
        int j = f % NF, ks = f / NF;
        int g = lane >> 2, t = lane & 3;
        int n = j * 8 + g;
#pragma unroll
        for (int r = 0; r < 2; r++) {
            int k = ks * 16 + 2 * t + 8 * r;
            pack_hl(W[k * N + n], W[(k + 1) * N + n], hi[idx * 2 + r], lo[idx * 2 + r]);
        }
    }
}

// 3-term split mma over one layer: D[NF][4] += (Ah+Al) @ Bh + Ah @ Bl
template <int KS, int NF>
__device__ __forceinline__ void layer_mma(float (&d)[NF][4],
                                          const uint32_t* __restrict__ fh,
                                          const uint32_t* __restrict__ fl,
                                          const uint32_t (&Ah)[KS * 4],
                                          const uint32_t (&Al)[KS * 4], int lane) {
#pragma unroll
    for (int j = 0; j < NF; j++) {
#pragma unroll
        for (int ks = 0; ks < KS; ks++) {
            int fi = ((ks * NF + j) * 32 + lane) * 2;
            uint2 bh = *(const uint2*)&fh[fi];
            uint2 bl = *(const uint2*)&fl[fi];
            mma16816(d[j], &Ah[ks * 4], bh.x, bh.y);
            mma16816(d[j], &Al[ks * 4], bh.x, bh.y);
            mma16816(d[j], &Ah[ks * 4], bl.x, bl.y);
        }
    }
}

// Epilogue: D (NF=2*KSN n-tiles) + bias -> relu -> hi/lo fp16 A frags for next layer.
// A reg mapping: a[ks*4+0] = (g, 2t..) of j=2ks ; +1 = (g+8,..) j=2ks ;
//                a[ks*4+2..3] same from j=2ks+1.
template <int KSN>
__device__ __forceinline__ void epi_relu(const float (&d)[2 * KSN][4],
                                         const float* __restrict__ bias, int lane,
                                         uint32_t (&Ah)[KSN * 4], uint32_t (&Al)[KSN * 4]) {
    int t = lane & 3;
#pragma unroll
    for (int ks = 0; ks < KSN; ks++) {
#pragma unroll
        for (int h = 0; h < 2; h++) {
            int j = 2 * ks + h;
            float2 b = *(const float2*)&bias[j * 8 + 2 * t];
            float f0 = fmaxf(d[j][0] + b.x, 0.0f);
            float f1 = fmaxf(d[j][1] + b.y, 0.0f);
            float f2 = fmaxf(d[j][2] + b.x, 0.0f);
            float f3 = fmaxf(d[j][3] + b.y, 0.0f);
            pack_hl(f0, f1, Ah[ks * 4 + h * 2 + 0], Al[ks * 4 + h * 2 + 0]);
            pack_hl(f2, f3, Ah[ks * 4 + h * 2 + 1], Al[ks * 4 + h * 2 + 1]);
        }
    }
}

__global__ void __launch_bounds__(THREADS, 4)
mlp_hmma_kernel(const float* __restrict__ x,
                const float* __restrict__ Wi, const float* __restrict__ bi,
                const float* __restrict__ W1, const float* __restrict__ b1,
                const float* __restrict__ W2, const float* __restrict__ b2,
                const float* __restrict__ Wo, const float* __restrict__ bo,
                float* __restrict__ out) {
    const int tid = threadIdx.x;
    const int wid = tid >> 5;
    const int lane = tid & 31;
    const int g = lane >> 2, t = lane & 3;

    // ---- stage weights (fragment-ordered, hi/lo split) + biases ----
    stage(Wi, 32, 64, sf1h, sf1l, tid);
    stage(W1, 64, 64, sf2h, sf2l, tid);
    stage(W2, 64, 64, sf3h, sf3l, tid);
    stage(Wo, 64, 16, sf4h, sf4l, tid);
    for (int i = tid; i < 64; i += THREADS) { sb1[i] = bi[i]; sb2[i] = b1[i]; sb3[i] = b2[i]; }
    if (tid < 16) sb4[tid] = bo[tid];
    __syncthreads();

    const int wstride = gridDim.x * WARPS;
    for (int wt = blockIdx.x * WARPS + wid; wt < WTILES; wt += wstride) {
        const size_t rowbase = (size_t)wt * 16;

        // ---- load x (16x32) as hi/lo A fragments (K=32 -> 2 ksteps) ----
        uint32_t Xh[8], Xl[8];
        {
            const float* xr0 = x + (rowbase + g) * 32;
            const float* xr8 = x + (rowbase + g + 8) * 32;
#pragma unroll
            for (int ks = 0; ks < 2; ks++) {
                float2 v0 = *(const float2*)&xr0[ks * 16 + 2 * t];
                float2 v1 = *(const float2*)&xr8[ks * 16 + 2 * t];
                float2 v2 = *(const float2*)&xr0[ks * 16 + 8 + 2 * t];
                float2 v3 = *(const float2*)&xr8[ks * 16 + 8 + 2 * t];
                pack_hl(v0.x, v0.y, Xh[ks * 4 + 0], Xl[ks * 4 + 0]);
                pack_hl(v1.x, v1.y, Xh[ks * 4 + 1], Xl[ks * 4 + 1]);
                pack_hl(v2.x, v2.y, Xh[ks * 4 + 2], Xl[ks * 4 + 2]);
                pack_hl(v3.x, v3.y, Xh[ks * 4 + 3], Xl[ks * 4 + 3]);
            }
        }

        float d[8][4];
        uint32_t Ah[16], Al[16];

        // ---- L1: 32 -> 64 ----
#pragma unroll
        for (int j = 0; j < 8; j++)
#pragma unroll
            for (int e = 0; e < 4; e++) d[j][e] = 0.0f;
        layer_mma<2, 8>(d, sf1h, sf1l, Xh, Xl, lane);
        epi_relu<4>(d, sb1, lane, Ah, Al);

        // ---- L2: 64 -> 64 ----
#pragma unroll
        for (int j = 0; j < 8; j++)
#pragma unroll
            for (int e = 0; e < 4; e++) d[j][e] = 0.0f;
        layer_mma<4, 8>(d, sf2h, sf2l, Ah, Al, lane);
        epi_relu<4>(d, sb2, lane, Ah, Al);

        // ---- L3: 64 -> 64 ----
#pragma unroll
        for (int j = 0; j < 8; j++)
#pragma unroll
            for (int e = 0; e < 4; e++) d[j][e] = 0.0f;
        layer_mma<4, 8>(d, sf3h, sf3l, Ah, Al, lane);
        epi_relu<4>(d, sb3, lane, Ah, Al);

        // ---- L4: 64 -> 16 (no relu) ----
        float d4[2][4];
#pragma unroll
        for (int j = 0; j < 2; j++)
#pragma unroll
            for (int e = 0; e < 4; e++) d4[j][e] = 0.0f;
        layer_mma<4, 2>(d4, sf4h, sf4l, Ah, Al, lane);

        // ---- write out: rows g, g+8; cols 8j+2t, +1 ----
        {
            float* o0 = out + (rowbase + g) * 16;
            float* o8 = out + (rowbase + g + 8) * 16;
#pragma unroll
            for (int j = 0; j < 2; j++) {
                float2 b = *(const float2*)&sb4[j * 8 + 2 * t];
                *(float2*)&o0[j * 8 + 2 * t] = make_float2(d4[j][0] + b.x, d4[j][1] + b.y);
                *(float2*)&o8[j * 8 + 2 * t] = make_float2(d4[j][2] + b.x, d4[j][3] + b.y);
            }
        }
    }
}

extern "C" void kernel_launch(void* const* d_in, const int* in_sizes, int n_in,
                              void* d_out, int out_size) {
    (void)in_sizes; (void)n_in; (void)out_size;
    const float* x  = (const float*)d_in[0];
    const float* Wi = (const float*)d_in[1];
    const float* bi = (const float*)d_in[2];
    const float* W1 = (const float*)d_in[3];
    const float* b1 = (const float*)d_in[4];
    const float* W2 = (const float*)d_in[5];
    const float* b2 = (const float*)d_in[6];
    const float* Wo = (const float*)d_in[7];
    const float* bo = (const float*)d_in[8];
    float* out = (float*)d_out;

    mlp_hmma_kernel<<<GRID, THREADS>>>(x, Wi, bi, W1, b1, W2, b2, Wo, bo, out);
}